// round 12
// baseline (speedup 1.0000x reference)
#include <cuda_runtime.h>
#include <cuda_bf16.h>
#include <cstdint>
#include <math.h>

// ---------------- problem constants ----------------
#define T_TOK 2048
#define H_DIM 2048
#define I_DIM 2048
#define N_EXP 16
#define TOPK  4
#define ALPHA 1.702f
#define LIMIT 7.0f
#define NPAIR (T_TOK * TOPK)   // 8192

#define BM 128
#define BK 32
#define STRIDE 36              // floats per smem row (padded)
#define NCHUNK (H_DIM / BK)    // 64
#define NSTG 3

#define ROW_F (128 * STRIDE)            // floats per 128-row tile = 4608
#define HROW_F (64 * STRIDE)            // floats per 64-row tile
#define GU_STG_F (ROW_F + 2 * HROW_F)   // A(128) | Bg(64) | Bu(64) = 9216 floats
#define DN_STG_F (2 * ROW_F)            // A | B = 9216 floats
#define GU_SMEM (1024 + NSTG * GU_STG_F * 4)  // 111,616 B
#define DN_SMEM (1024 + NSTG * DN_STG_F * 4)  // 111,616 B

// ---------------- scratch (device globals) ----------------
__device__ float g_hbuf[(size_t)NPAIR * I_DIM];   // activated hidden per pair (tf32-rounded)
__device__ float g_outp[(size_t)NPAIR * H_DIM];   // per-pair down output
__device__ int   g_pair_token[NPAIR];
__device__ int   g_top_idx[T_TOK * TOPK];
__device__ float g_top_prob[T_TOK * TOPK];
__device__ int   g_pidx[T_TOK * TOPK];
__device__ int   g_offsets[N_EXP + 1];

// ---------------- PTX helpers ----------------
__device__ __forceinline__ uint32_t smem_u32(const void* p) {
    uint32_t r;
    asm("{ .reg .u64 t; cvta.to.shared.u64 t, %1; cvt.u32.u64 %0, t; }" : "=r"(r) : "l"(p));
    return r;
}
__device__ __forceinline__ void cp16(uint32_t dst, const void* src) {
    asm volatile("cp.async.cg.shared.global [%0], [%1], 16;" :: "r"(dst), "l"(src) : "memory");
}
// arrive on mbarrier when all of this thread's prior cp.asyncs have completed (no count inc)
__device__ __forceinline__ void cp_arrive_noinc(uint32_t mbar) {
    asm volatile("cp.async.mbarrier.arrive.noinc.shared.b64 [%0];" :: "r"(mbar) : "memory");
}
__device__ __forceinline__ void mbar_init(uint32_t mbar, uint32_t cnt) {
    asm volatile("mbarrier.init.shared.b64 [%0], %1;" :: "r"(mbar), "r"(cnt) : "memory");
}
__device__ __forceinline__ void mbar_arrive(uint32_t mbar) {
    asm volatile("mbarrier.arrive.shared.b64 _, [%0];" :: "r"(mbar) : "memory");
}
__device__ __forceinline__ void mbar_wait(uint32_t mbar, uint32_t phase) {
    asm volatile(
        "{ .reg .pred P;\n"
        "WL_%=: mbarrier.try_wait.parity.acquire.cta.shared::cta.b64 P, [%0], %1, 0x989680;\n"
        "@P bra.uni WD_%=;\n"
        "bra.uni WL_%=;\n"
        "WD_%=: }"
        :: "r"(mbar), "r"(phase) : "memory");
}

__device__ __forceinline__ void ldsm_x4(uint32_t addr, uint32_t& r0, uint32_t& r1, uint32_t& r2, uint32_t& r3) {
    asm volatile("ldmatrix.sync.aligned.m8n8.x4.shared.b16 {%0,%1,%2,%3}, [%4];"
                 : "=r"(r0), "=r"(r1), "=r"(r2), "=r"(r3) : "r"(addr));
}
__device__ __forceinline__ void mma_tf32(float* d, uint32_t a0, uint32_t a1, uint32_t a2, uint32_t a3,
                                         uint32_t b0, uint32_t b1) {
    asm volatile("mma.sync.aligned.m16n8k8.row.col.f32.tf32.tf32.f32 "
                 "{%0,%1,%2,%3}, {%4,%5,%6,%7}, {%8,%9}, {%0,%1,%2,%3};"
                 : "+f"(d[0]), "+f"(d[1]), "+f"(d[2]), "+f"(d[3])
                 : "r"(a0), "r"(a1), "r"(a2), "r"(a3), "r"(b0), "r"(b1));
}
// RNA-to-tf32 in-register: add half-ulp; the MMA HW's RZ truncation completes the round.
#define RNA4(r0, r1, r2, r3) { r0 += 0x1000u; r1 += 0x1000u; r2 += 0x1000u; r3 += 0x1000u; }
// full round (for values stored to memory)
__device__ __forceinline__ uint32_t rnd_tf32(uint32_t u) { return (u + 0x1000u) & 0xFFFFE000u; }

// ---------------- K1: router (no atomics) ----------------
__global__ void router_kernel(const float* __restrict__ x,
                              const float* __restrict__ rw,
                              const float* __restrict__ rb,
                              float* __restrict__ score_out) {
    __shared__ float xs[H_DIM];
    __shared__ float logits[N_EXP];
    int t = blockIdx.x;
    int tid = threadIdx.x;
    const float* xr = x + (size_t)t * H_DIM;
    for (int h = tid; h < H_DIM; h += 128) xs[h] = xr[h];
    __syncthreads();

    int warp = tid >> 5, lane = tid & 31;
    for (int e = warp * 4; e < warp * 4 + 4; e++) {
        const float* w = rw + (size_t)e * H_DIM;
        float acc = 0.f;
        for (int h = lane; h < H_DIM; h += 32) acc += xs[h] * w[h];
        #pragma unroll
        for (int s = 16; s > 0; s >>= 1) acc += __shfl_xor_sync(0xffffffffu, acc, s);
        if (lane == 0) logits[e] = acc + rb[e];
    }
    __syncthreads();

    if (tid == 0) {
        float vals[TOPK]; int idx[TOPK];
        bool used[N_EXP];
        #pragma unroll
        for (int e = 0; e < N_EXP; e++) used[e] = false;
        #pragma unroll
        for (int s = 0; s < TOPK; s++) {
            float best = -INFINITY; int bi = 0;
            for (int e = 0; e < N_EXP; e++)
                if (!used[e] && logits[e] > best) { best = logits[e]; bi = e; }
            used[bi] = true; vals[s] = best; idx[s] = bi;
        }
        float m = vals[0];
        float se = 0.f, pe[TOPK];
        #pragma unroll
        for (int s = 0; s < TOPK; s++) { pe[s] = expf(vals[s] - m); se += pe[s]; }
        float inv = 1.f / se;
        float* row = score_out + (size_t)t * N_EXP;
        #pragma unroll
        for (int e = 0; e < N_EXP; e++) row[e] = 0.f;
        #pragma unroll
        for (int s = 0; s < TOPK; s++) {
            float p = pe[s] * inv;
            row[idx[s]] = p;
            g_top_idx[t * TOPK + s] = idx[s];
            g_top_prob[t * TOPK + s] = p;
        }
    }
}

// ---------------- K2: fused histogram + scan + assign (single block) ----------------
__global__ __launch_bounds__(1024)
void route_post() {
    __shared__ int cnts[N_EXP];
    __shared__ int offs[N_EXP];
    __shared__ int fill[N_EXP];
    int tid = threadIdx.x;
    if (tid < N_EXP) { cnts[tid] = 0; fill[tid] = 0; }
    __syncthreads();
    for (int i = tid; i < NPAIR; i += 1024)
        atomicAdd(&cnts[g_top_idx[i]], 1);
    __syncthreads();
    if (tid == 0) {
        int off = 0;
        for (int e = 0; e < N_EXP; e++) { offs[e] = off; g_offsets[e] = off; off += cnts[e]; }
        g_offsets[N_EXP] = off;
    }
    __syncthreads();
    for (int i = tid; i < NPAIR; i += 1024) {
        int e = g_top_idx[i];
        int pos = atomicAdd(&fill[e], 1);
        int pid = offs[e] + pos;
        g_pair_token[pid] = i >> 2;     // token index
        g_pidx[i] = pid;
    }
}

// ---------------- K4: gate+up mma.sync tf32 GEMM + GLU (128 thr, warp 64x32x2, 2 CTA/SM) ----------------
__global__ __launch_bounds__(128, 2)
void gateup_mma(const float* __restrict__ x,
                const float* __restrict__ gate_w, const float* __restrict__ up_w,
                const float* __restrict__ gate_b, const float* __restrict__ up_b) {
    int e = blockIdx.z;
    int base = g_offsets[e];
    int cnt  = g_offsets[e + 1] - base;
    int m0 = blockIdx.y * BM;
    if (m0 >= cnt) return;
    int n0 = blockIdx.x * 64;

    extern __shared__ char smem[];
    uint32_t sb0 = smem_u32(smem);
    uint32_t mb_full = sb0;          // 3 x 8B
    uint32_t mb_empty = sb0 + 24;    // 3 x 8B
    int* toks = (int*)(smem + 64);
    float* stages = (float*)(smem + 1024);
    uint32_t sb = sb0 + 1024;

    int tid = threadIdx.x, wid = tid >> 5, lane = tid & 31;
    int wm = wid & 1, wn = wid >> 1;          // 2 m-halves x 2 n-halves (32 cols each)

    {
        int m = m0 + tid;
        toks[tid] = (m < cnt) ? g_pair_token[base + m] : g_pair_token[base];
    }
    if (tid == 0) {
        #pragma unroll
        for (int s = 0; s < NSTG; s++) { mbar_init(mb_full + 8 * s, 128); mbar_init(mb_empty + 8 * s, 128); }
    }
    __syncthreads();

    const float* gwe = gate_w + (size_t)e * I_DIM * H_DIM;
    const float* uwe = up_w   + (size_t)e * I_DIM * H_DIM;

    int rr  = tid >> 3;     // 0..15
    int c16 = tid & 7;      // 16B chunk

    auto load_stage = [&](int s, int k0) {
        float* A = stages + s * GU_STG_F;
        float* Bg = A + ROW_F;
        float* Bu = Bg + HROW_F;
        uint32_t au = smem_u32(A), gu = smem_u32(Bg), uu = smem_u32(Bu);
        #pragma unroll
        for (int rep = 0; rep < 8; rep++) {
            int row = rr + rep * 16;
            uint32_t d = (row * STRIDE + c16 * 4) * 4;
            cp16(au + d, x + (size_t)toks[row] * H_DIM + k0 + c16 * 4);
        }
        #pragma unroll
        for (int rep = 0; rep < 4; rep++) {
            int row = rr + rep * 16;
            uint32_t d = (row * STRIDE + c16 * 4) * 4;
            cp16(gu + d, gwe + (size_t)(n0 + row) * H_DIM + k0 + c16 * 4);
            cp16(uu + d, uwe + (size_t)(n0 + row) * H_DIM + k0 + c16 * 4);
        }
    };

    // pipeline cursors
    int ps = 0, pp = 1;    // producer stage / phase (phase 1: first empty-waits pass)
    int cs = 0, cphase = 0;

    // prime 2 chunks
    #pragma unroll
    for (int p = 0; p < 2; p++) {
        mbar_wait(mb_empty + 8 * ps, pp);
        load_stage(ps, p * BK);
        cp_arrive_noinc(mb_full + 8 * ps);
        if (++ps == NSTG) { ps = 0; pp ^= 1; }
    }

    // accumulators: warp tile 64m x 32n for each of gate/up
    float dg[4][4][4], du[4][4][4];
    #pragma unroll
    for (int a = 0; a < 4; a++)
        #pragma unroll
        for (int b = 0; b < 4; b++)
            #pragma unroll
            for (int q = 0; q < 4; q++) { dg[a][b][q] = 0.f; du[a][b][q] = 0.f; }

    // ldmatrix lane offsets (bytes)
    int lr = lane & 7, hi8 = (lane >> 3) & 1, hi16 = (lane >> 4) & 1;
    uint32_t a_lane = ((lr + hi8 * 8) * STRIDE + hi16 * 4) * 4;   // A x4
    uint32_t b_lane = ((lr + hi16 * 8) * STRIDE + hi8 * 4) * 4;   // B x4 (two n8 tiles)

    // fragment loaders (double-buffered in registers)
    auto loadB = [&](uint32_t Gs, uint32_t Us, int ks, uint32_t (&bg)[4][2], uint32_t (&bu)[4][2]) {
        int k0 = ks * 8;
        #pragma unroll
        for (int np = 0; np < 2; np++) {
            uint32_t boff = ((wn * 32 + np * 16) * STRIDE + k0) * 4 + b_lane;
            ldsm_x4(Gs + boff, bg[2*np][0], bg[2*np][1], bg[2*np+1][0], bg[2*np+1][1]);
            RNA4(bg[2*np][0], bg[2*np][1], bg[2*np+1][0], bg[2*np+1][1]);
            ldsm_x4(Us + boff, bu[2*np][0], bu[2*np][1], bu[2*np+1][0], bu[2*np+1][1]);
            RNA4(bu[2*np][0], bu[2*np][1], bu[2*np+1][0], bu[2*np+1][1]);
        }
    };
    auto loadA = [&](uint32_t As, int ks, int mi, uint32_t (&a)[4]) {
        uint32_t aoff = ((wm * 64 + mi * 16) * STRIDE + ks * 8) * 4 + a_lane;
        ldsm_x4(As + aoff, a[0], a[1], a[2], a[3]);
        RNA4(a[0], a[1], a[2], a[3]);   // x is not pre-rounded
    };

    for (int c = 0; c < NCHUNK; c++) {
        int nc = c + 2;
        if (nc < NCHUNK) {
            mbar_wait(mb_empty + 8 * ps, pp);
            load_stage(ps, nc * BK);
            cp_arrive_noinc(mb_full + 8 * ps);
            if (++ps == NSTG) { ps = 0; pp ^= 1; }
        }
        mbar_wait(mb_full + 8 * cs, cphase);
        uint32_t As = sb + (uint32_t)(cs * GU_STG_F) * 4;
        uint32_t Gs = As + ROW_F * 4;
        uint32_t Us = Gs + HROW_F * 4;

        uint32_t bg[2][4][2], bu[2][4][2], av[2][4];
        loadB(Gs, Us, 0, bg[0], bu[0]);
        loadA(As, 0, 0, av[0]);
        #pragma unroll
        for (int ks = 0; ks < 4; ks++) {
            int cb = ks & 1;
            #pragma unroll
            for (int mi = 0; mi < 4; mi++) {
                int ca = mi & 1;
                if (mi < 3) loadA(As, ks, mi + 1, av[ca ^ 1]);
                else if (ks < 3) { loadB(Gs, Us, ks + 1, bg[cb ^ 1], bu[cb ^ 1]); loadA(As, ks + 1, 0, av[ca ^ 1]); }
                #pragma unroll
                for (int ni = 0; ni < 4; ni++) {
                    mma_tf32(dg[mi][ni], av[ca][0], av[ca][1], av[ca][2], av[ca][3], bg[cb][ni][0], bg[cb][ni][1]);
                    mma_tf32(du[mi][ni], av[ca][0], av[ca][1], av[ca][2], av[ca][3], bu[cb][ni][0], bu[cb][ni][1]);
                }
            }
        }
        mbar_arrive(mb_empty + 8 * cs);
        if (++cs == NSTG) { cs = 0; cphase ^= 1; }
    }

    // ---- epilogue: bias + GLU, store rounded h ----
    int g = lane >> 2, tq = lane & 3;
    #pragma unroll
    for (int mi = 0; mi < 4; mi++) {
        #pragma unroll
        for (int half = 0; half < 2; half++) {
            int m = m0 + wm * 64 + mi * 16 + g + half * 8;
            if (m >= cnt) continue;
            size_t rowbase = (size_t)(base + m) * I_DIM;
            #pragma unroll
            for (int ni = 0; ni < 4; ni++) {
                int col = n0 + wn * 32 + ni * 8 + 2 * tq;
                #pragma unroll
                for (int q = 0; q < 2; q++) {
                    float gv = dg[mi][ni][half * 2 + q] + gate_b[(size_t)e * I_DIM + col + q];
                    float uv = du[mi][ni][half * 2 + q] + up_b[(size_t)e * I_DIM + col + q];
                    uv = fminf(fmaxf(uv, -LIMIT), LIMIT);
                    gv = fminf(gv, LIMIT);
                    float glu = gv / (1.0f + __expf(-ALPHA * gv));
                    float h = (uv + 1.0f) * glu;
                    g_hbuf[rowbase + col + q] = __uint_as_float(rnd_tf32(__float_as_uint(h)));
                }
            }
        }
    }
}

// ---------------- K5: down mma.sync tf32 GEMM (128 thr, warp 64x64, 2 CTA/SM) ----------------
__global__ __launch_bounds__(128, 2)
void down_mma(const float* __restrict__ down_w, const float* __restrict__ down_b) {
    int e = blockIdx.z;
    int base = g_offsets[e];
    int cnt  = g_offsets[e + 1] - base;
    int m0 = blockIdx.y * BM;
    if (m0 >= cnt) return;
    int n0 = blockIdx.x * 128;

    extern __shared__ char smem[];
    uint32_t sb0 = smem_u32(smem);
    uint32_t mb_full = sb0;
    uint32_t mb_empty = sb0 + 24;
    float* stages = (float*)(smem + 1024);
    uint32_t sb = sb0 + 1024;

    int tid = threadIdx.x, wid = tid >> 5, lane = tid & 31;
    int wm = wid & 1, wn = wid >> 1;   // 2 x 2 warps, tile 64m x 64n

    if (tid == 0) {
        #pragma unroll
        for (int s = 0; s < NSTG; s++) { mbar_init(mb_full + 8 * s, 128); mbar_init(mb_empty + 8 * s, 128); }
    }
    __syncthreads();

    const float* dwe = down_w + (size_t)e * H_DIM * I_DIM;

    int rr  = tid >> 3;   // 0..15
    int c16 = tid & 7;

    auto load_stage = [&](int s, int k0) {
        float* A = stages + s * DN_STG_F;
        float* B = A + ROW_F;
        uint32_t au = smem_u32(A), bu = smem_u32(B);
        #pragma unroll
        for (int rep = 0; rep < 8; rep++) {
            int row = rr + rep * 16;
            uint32_t d = (row * STRIDE + c16 * 4) * 4;
            int ar = (m0 + row < cnt) ? (base + m0 + row) : base;
            cp16(au + d, g_hbuf + (size_t)ar * I_DIM + k0 + c16 * 4);
            cp16(bu + d, dwe + (size_t)(n0 + row) * I_DIM + k0 + c16 * 4);
        }
    };

    int ps = 0, pp = 1;
    int cs = 0, cphase = 0;

    #pragma unroll
    for (int p = 0; p < 2; p++) {
        mbar_wait(mb_empty + 8 * ps, pp);
        load_stage(ps, p * BK);
        cp_arrive_noinc(mb_full + 8 * ps);
        if (++ps == NSTG) { ps = 0; pp ^= 1; }
    }

    float dd[4][8][4];
    #pragma unroll
    for (int a = 0; a < 4; a++)
        #pragma unroll
        for (int b = 0; b < 8; b++)
            #pragma unroll
            for (int q = 0; q < 4; q++) dd[a][b][q] = 0.f;

    int lr = lane & 7, hi8 = (lane >> 3) & 1, hi16 = (lane >> 4) & 1;
    uint32_t a_lane = ((lr + hi8 * 8) * STRIDE + hi16 * 4) * 4;
    uint32_t b_lane = ((lr + hi16 * 8) * STRIDE + hi8 * 4) * 4;

    auto loadB = [&](uint32_t Bs, int ks, uint32_t (&b)[8][2]) {
        int k0 = ks * 8;
        #pragma unroll
        for (int np = 0; np < 4; np++) {
            uint32_t boff = ((wn * 64 + np * 16) * STRIDE + k0) * 4 + b_lane;
            ldsm_x4(Bs + boff, b[2*np][0], b[2*np][1], b[2*np+1][0], b[2*np+1][1]);
            RNA4(b[2*np][0], b[2*np][1], b[2*np+1][0], b[2*np+1][1]);
        }
    };
    auto loadA = [&](uint32_t As, int ks, int mi, uint32_t (&a)[4]) {
        uint32_t aoff = ((wm * 64 + mi * 16) * STRIDE + ks * 8) * 4 + a_lane;
        ldsm_x4(As + aoff, a[0], a[1], a[2], a[3]);
        // A (g_hbuf) is already tf32-rounded; no RNA needed
    };

    for (int c = 0; c < NCHUNK; c++) {
        int nc = c + 2;
        if (nc < NCHUNK) {
            mbar_wait(mb_empty + 8 * ps, pp);
            load_stage(ps, nc * BK);
            cp_arrive_noinc(mb_full + 8 * ps);
            if (++ps == NSTG) { ps = 0; pp ^= 1; }
        }
        mbar_wait(mb_full + 8 * cs, cphase);
        uint32_t As = sb + (uint32_t)(cs * DN_STG_F) * 4;
        uint32_t Bs = As + ROW_F * 4;

        uint32_t bb[2][8][2], av[2][4];
        loadB(Bs, 0, bb[0]);
        loadA(As, 0, 0, av[0]);
        #pragma unroll
        for (int ks = 0; ks < 4; ks++) {
            int cb = ks & 1;
            #pragma unroll
            for (int mi = 0; mi < 4; mi++) {
                int ca = mi & 1;
                if (mi < 3) loadA(As, ks, mi + 1, av[ca ^ 1]);
                else if (ks < 3) { loadB(Bs, ks + 1, bb[cb ^ 1]); loadA(As, ks + 1, 0, av[ca ^ 1]); }
                #pragma unroll
                for (int ni = 0; ni < 8; ni++)
                    mma_tf32(dd[mi][ni], av[ca][0], av[ca][1], av[ca][2], av[ca][3], bb[cb][ni][0], bb[cb][ni][1]);
            }
        }
        mbar_arrive(mb_empty + 8 * cs);
        if (++cs == NSTG) { cs = 0; cphase ^= 1; }
    }

    int g = lane >> 2, tq = lane & 3;
    #pragma unroll
    for (int mi = 0; mi < 4; mi++) {
        #pragma unroll
        for (int half = 0; half < 2; half++) {
            int m = m0 + wm * 64 + mi * 16 + g + half * 8;
            if (m >= cnt) continue;
            size_t rowbase = (size_t)(base + m) * H_DIM;
            #pragma unroll
            for (int ni = 0; ni < 8; ni++) {
                int col = n0 + wn * 64 + ni * 8 + 2 * tq;
                float2 v;
                v.x = dd[mi][ni][half * 2 + 0] + down_b[(size_t)e * H_DIM + col];
                v.y = dd[mi][ni][half * 2 + 1] + down_b[(size_t)e * H_DIM + col + 1];
                *(float2*)&g_outp[rowbase + col] = v;
            }
        }
    }
}

// ---------------- K6: combine ----------------
__global__ void combine_kernel(float* __restrict__ out) {
    int t = blockIdx.y;
    int h = blockIdx.x * blockDim.x + threadIdx.x;
    float acc = 0.f;
    #pragma unroll
    for (int s = 0; s < TOPK; s++) {
        float p = g_top_prob[t * TOPK + s];
        int pid = g_pidx[t * TOPK + s];
        acc += p * g_outp[(size_t)pid * H_DIM + h];
    }
    out[(size_t)t * H_DIM + h] = acc;
}

// ---------------- launch ----------------
extern "C" void kernel_launch(void* const* d_in, const int* in_sizes, int n_in,
                              void* d_out, int out_size) {
    const float* hidden   = (const float*)d_in[0];
    const float* router_w = (const float*)d_in[1];
    const float* router_b = (const float*)d_in[2];
    const float* gate_w   = (const float*)d_in[3];
    const float* gate_b   = (const float*)d_in[4];
    const float* up_w     = (const float*)d_in[5];
    const float* up_b     = (const float*)d_in[6];
    const float* down_w   = (const float*)d_in[7];
    const float* down_b   = (const float*)d_in[8];

    float* next_states = (float*)d_out;
    float* score_out   = (float*)d_out + (size_t)T_TOK * H_DIM;

    static bool attr_done = false;
    if (!attr_done) {
        cudaFuncSetAttribute(gateup_mma, cudaFuncAttributeMaxDynamicSharedMemorySize, GU_SMEM);
        cudaFuncSetAttribute(down_mma,   cudaFuncAttributeMaxDynamicSharedMemorySize, DN_SMEM);
        attr_done = true;
    }

    router_kernel<<<T_TOK, 128>>>(hidden, router_w, router_b, score_out);
    route_post<<<1, 1024>>>();

    dim3 gu_grid(I_DIM / 64, NPAIR / BM, N_EXP);
    gateup_mma<<<gu_grid, 128, GU_SMEM>>>(hidden, gate_w, up_w, gate_b, up_b);

    dim3 dn_grid(H_DIM / 128, NPAIR / BM, N_EXP);
    down_mma<<<dn_grid, 128, DN_SMEM>>>(down_w, down_b);

    dim3 cb_grid(H_DIM / 256, T_TOK);
    combine_kernel<<<cb_grid, 256>>>(next_states);
}

// round 13
// speedup vs baseline: 1.0386x; 1.0386x over previous
#include <cuda_runtime.h>
#include <cuda_bf16.h>
#include <cstdint>
#include <math.h>

// ---------------- problem constants ----------------
#define T_TOK 2048
#define H_DIM 2048
#define I_DIM 2048
#define N_EXP 16
#define TOPK  4
#define ALPHA 1.702f
#define LIMIT 7.0f
#define NPAIR (T_TOK * TOPK)   // 8192

#define BM 128
#define BK 32
#define STRIDE 36              // floats per smem row (padded)
#define NCHUNK (H_DIM / BK)    // 64
#define NSTG 3

#define ROW_F (128 * STRIDE)            // floats per 128-row tile = 4608
#define HROW_F (64 * STRIDE)            // floats per 64-row tile
#define GU_STG_F (ROW_F + 2 * HROW_F)   // A(128) | Bg(64) | Bu(64) = 9216 floats
#define DN_STG_F (2 * ROW_F)            // A | B = 9216 floats
#define GU_SMEM (1024 + NSTG * GU_STG_F * 4)  // 111,616 B
#define DN_SMEM (1024 + NSTG * DN_STG_F * 4)  // 111,616 B

// ---------------- scratch (device globals) ----------------
__device__ float g_hbuf[(size_t)NPAIR * I_DIM];   // activated hidden per pair (tf32-rounded)
__device__ float g_outp[(size_t)NPAIR * H_DIM];   // per-pair down output
__device__ int   g_pair_token[NPAIR];
__device__ int   g_top_idx[T_TOK * TOPK];
__device__ float g_top_prob[T_TOK * TOPK];
__device__ int   g_pidx[T_TOK * TOPK];
__device__ int   g_offsets[N_EXP + 1];

// ---------------- PTX helpers ----------------
__device__ __forceinline__ uint32_t smem_u32(const void* p) {
    uint32_t r;
    asm("{ .reg .u64 t; cvta.to.shared.u64 t, %1; cvt.u32.u64 %0, t; }" : "=r"(r) : "l"(p));
    return r;
}
__device__ __forceinline__ void cp16(uint32_t dst, const void* src) {
    asm volatile("cp.async.cg.shared.global [%0], [%1], 16;" :: "r"(dst), "l"(src) : "memory");
}
// arrive on mbarrier when all of this thread's prior cp.asyncs have completed (no count inc)
__device__ __forceinline__ void cp_arrive_noinc(uint32_t mbar) {
    asm volatile("cp.async.mbarrier.arrive.noinc.shared.b64 [%0];" :: "r"(mbar) : "memory");
}
__device__ __forceinline__ void mbar_init(uint32_t mbar, uint32_t cnt) {
    asm volatile("mbarrier.init.shared.b64 [%0], %1;" :: "r"(mbar), "r"(cnt) : "memory");
}
__device__ __forceinline__ void mbar_arrive(uint32_t mbar) {
    asm volatile("mbarrier.arrive.shared.b64 _, [%0];" :: "r"(mbar) : "memory");
}
__device__ __forceinline__ void mbar_wait(uint32_t mbar, uint32_t phase) {
    asm volatile(
        "{ .reg .pred P;\n"
        "WL_%=: mbarrier.try_wait.parity.acquire.cta.shared::cta.b64 P, [%0], %1, 0x989680;\n"
        "@P bra.uni WD_%=;\n"
        "bra.uni WL_%=;\n"
        "WD_%=: }"
        :: "r"(mbar), "r"(phase) : "memory");
}

__device__ __forceinline__ void ldsm_x4(uint32_t addr, uint32_t& r0, uint32_t& r1, uint32_t& r2, uint32_t& r3) {
    asm volatile("ldmatrix.sync.aligned.m8n8.x4.shared.b16 {%0,%1,%2,%3}, [%4];"
                 : "=r"(r0), "=r"(r1), "=r"(r2), "=r"(r3) : "r"(addr));
}
__device__ __forceinline__ void mma_tf32(float* d, uint32_t a0, uint32_t a1, uint32_t a2, uint32_t a3,
                                         uint32_t b0, uint32_t b1) {
    asm volatile("mma.sync.aligned.m16n8k8.row.col.f32.tf32.tf32.f32 "
                 "{%0,%1,%2,%3}, {%4,%5,%6,%7}, {%8,%9}, {%0,%1,%2,%3};"
                 : "+f"(d[0]), "+f"(d[1]), "+f"(d[2]), "+f"(d[3])
                 : "r"(a0), "r"(a1), "r"(a2), "r"(a3), "r"(b0), "r"(b1));
}
// RNA-to-tf32 in-register: add half-ulp; the MMA HW's RZ truncation completes the round.
#define RNA4(r0, r1, r2, r3) { r0 += 0x1000u; r1 += 0x1000u; r2 += 0x1000u; r3 += 0x1000u; }
// full round (for values stored to memory)
__device__ __forceinline__ uint32_t rnd_tf32(uint32_t u) { return (u + 0x1000u) & 0xFFFFE000u; }

// ---------------- K1: router (no atomics) ----------------
__global__ void router_kernel(const float* __restrict__ x,
                              const float* __restrict__ rw,
                              const float* __restrict__ rb,
                              float* __restrict__ score_out) {
    __shared__ float xs[H_DIM];
    __shared__ float logits[N_EXP];
    int t = blockIdx.x;
    int tid = threadIdx.x;
    const float* xr = x + (size_t)t * H_DIM;
    for (int h = tid; h < H_DIM; h += 128) xs[h] = xr[h];
    __syncthreads();

    int warp = tid >> 5, lane = tid & 31;
    for (int e = warp * 4; e < warp * 4 + 4; e++) {
        const float* w = rw + (size_t)e * H_DIM;
        float acc = 0.f;
        for (int h = lane; h < H_DIM; h += 32) acc += xs[h] * w[h];
        #pragma unroll
        for (int s = 16; s > 0; s >>= 1) acc += __shfl_xor_sync(0xffffffffu, acc, s);
        if (lane == 0) logits[e] = acc + rb[e];
    }
    __syncthreads();

    if (tid == 0) {
        float vals[TOPK]; int idx[TOPK];
        bool used[N_EXP];
        #pragma unroll
        for (int e = 0; e < N_EXP; e++) used[e] = false;
        #pragma unroll
        for (int s = 0; s < TOPK; s++) {
            float best = -INFINITY; int bi = 0;
            for (int e = 0; e < N_EXP; e++)
                if (!used[e] && logits[e] > best) { best = logits[e]; bi = e; }
            used[bi] = true; vals[s] = best; idx[s] = bi;
        }
        float m = vals[0];
        float se = 0.f, pe[TOPK];
        #pragma unroll
        for (int s = 0; s < TOPK; s++) { pe[s] = expf(vals[s] - m); se += pe[s]; }
        float inv = 1.f / se;
        float* row = score_out + (size_t)t * N_EXP;
        #pragma unroll
        for (int e = 0; e < N_EXP; e++) row[e] = 0.f;
        #pragma unroll
        for (int s = 0; s < TOPK; s++) {
            float p = pe[s] * inv;
            row[idx[s]] = p;
            g_top_idx[t * TOPK + s] = idx[s];
            g_top_prob[t * TOPK + s] = p;
        }
    }
}

// ---------------- K2: fused histogram + scan + assign (single block) ----------------
__global__ __launch_bounds__(1024)
void route_post() {
    __shared__ int cnts[N_EXP];
    __shared__ int offs[N_EXP];
    __shared__ int fill[N_EXP];
    int tid = threadIdx.x;
    if (tid < N_EXP) { cnts[tid] = 0; fill[tid] = 0; }
    __syncthreads();
    for (int i = tid; i < NPAIR; i += 1024)
        atomicAdd(&cnts[g_top_idx[i]], 1);
    __syncthreads();
    if (tid == 0) {
        int off = 0;
        for (int e = 0; e < N_EXP; e++) { offs[e] = off; g_offsets[e] = off; off += cnts[e]; }
        g_offsets[N_EXP] = off;
    }
    __syncthreads();
    for (int i = tid; i < NPAIR; i += 1024) {
        int e = g_top_idx[i];
        int pos = atomicAdd(&fill[e], 1);
        int pid = offs[e] + pos;
        g_pair_token[pid] = i >> 2;     // token index
        g_pidx[i] = pid;
    }
}

// ---------------- K4: gate+up mma.sync tf32 GEMM + GLU (256 thr, 2x4 warps, BN=64, 2 CTA/SM) ----------------
__global__ __launch_bounds__(256, 2)
void gateup_mma(const float* __restrict__ x,
                const float* __restrict__ gate_w, const float* __restrict__ up_w,
                const float* __restrict__ gate_b, const float* __restrict__ up_b) {
    int e = blockIdx.z;
    int base = g_offsets[e];
    int cnt  = g_offsets[e + 1] - base;
    int m0 = blockIdx.y * BM;
    if (m0 >= cnt) return;
    int n0 = blockIdx.x * 64;

    extern __shared__ char smem[];
    uint32_t sb0 = smem_u32(smem);
    uint32_t mb_full = sb0;          // 3 x 8B
    uint32_t mb_empty = sb0 + 24;    // 3 x 8B
    int* toks = (int*)(smem + 64);
    float* stages = (float*)(smem + 1024);
    uint32_t sb = sb0 + 1024;

    int tid = threadIdx.x, wid = tid >> 5, lane = tid & 31;
    int wm = wid & 1, wn = wid >> 1;          // 2 m-halves x 4 n-quarters (16 cols each)

    if (tid < 128) {
        int m = m0 + tid;
        toks[tid] = (m < cnt) ? g_pair_token[base + m] : g_pair_token[base];
    }
    if (tid == 0) {
        #pragma unroll
        for (int s = 0; s < NSTG; s++) { mbar_init(mb_full + 8 * s, 256); mbar_init(mb_empty + 8 * s, 256); }
    }
    __syncthreads();

    const float* gwe = gate_w + (size_t)e * I_DIM * H_DIM;
    const float* uwe = up_w   + (size_t)e * I_DIM * H_DIM;

    int rr  = tid >> 3;     // 0..31
    int c16 = tid & 7;      // 16B chunk

    auto load_stage = [&](int s, int k0) {
        float* A = stages + s * GU_STG_F;
        float* Bg = A + ROW_F;
        float* Bu = Bg + HROW_F;
        uint32_t au = smem_u32(A), gu = smem_u32(Bg), uu = smem_u32(Bu);
        #pragma unroll
        for (int rep = 0; rep < 4; rep++) {
            int row = rr + rep * 32;
            uint32_t d = (row * STRIDE + c16 * 4) * 4;
            cp16(au + d, x + (size_t)toks[row] * H_DIM + k0 + c16 * 4);
        }
        #pragma unroll
        for (int rep = 0; rep < 2; rep++) {
            int row = rr + rep * 32;
            uint32_t d = (row * STRIDE + c16 * 4) * 4;
            cp16(gu + d, gwe + (size_t)(n0 + row) * H_DIM + k0 + c16 * 4);
            cp16(uu + d, uwe + (size_t)(n0 + row) * H_DIM + k0 + c16 * 4);
        }
    };

    // pipeline cursors
    int ps = 0, pp = 1;    // producer stage / phase (phase 1: first empty-waits pass)
    int cs = 0, cphase = 0;

    // prime 2 chunks
    #pragma unroll
    for (int p = 0; p < 2; p++) {
        mbar_wait(mb_empty + 8 * ps, pp);
        load_stage(ps, p * BK);
        cp_arrive_noinc(mb_full + 8 * ps);
        if (++ps == NSTG) { ps = 0; pp ^= 1; }
    }

    // accumulators: warp tile 64m x 16n for each of gate/up
    float dg[4][2][4], du[4][2][4];
    #pragma unroll
    for (int a = 0; a < 4; a++)
        #pragma unroll
        for (int b = 0; b < 2; b++)
            #pragma unroll
            for (int q = 0; q < 4; q++) { dg[a][b][q] = 0.f; du[a][b][q] = 0.f; }

    // ldmatrix lane offsets (bytes)
    int lr = lane & 7, hi8 = (lane >> 3) & 1, hi16 = (lane >> 4) & 1;
    uint32_t a_lane = ((lr + hi8 * 8) * STRIDE + hi16 * 4) * 4;   // A x4
    uint32_t b_lane = ((lr + hi16 * 8) * STRIDE + hi8 * 4) * 4;   // B x4 (two n8 tiles)

    for (int c = 0; c < NCHUNK; c++) {
        int nc = c + 2;
        if (nc < NCHUNK) {
            mbar_wait(mb_empty + 8 * ps, pp);
            load_stage(ps, nc * BK);
            cp_arrive_noinc(mb_full + 8 * ps);
            if (++ps == NSTG) { ps = 0; pp ^= 1; }
        }
        mbar_wait(mb_full + 8 * cs, cphase);
        // compute on stage cs
        uint32_t As = sb + (uint32_t)(cs * GU_STG_F) * 4;
        uint32_t Gs = As + ROW_F * 4;
        uint32_t Us = Gs + HROW_F * 4;
        #pragma unroll
        for (int ks = 0; ks < 4; ks++) {
            int k0 = ks * 8;
            uint32_t bg[2][2], bu[2][2];
            uint32_t boff = (wn * 16 * STRIDE + k0) * 4 + b_lane;
            ldsm_x4(Gs + boff, bg[0][0], bg[0][1], bg[1][0], bg[1][1]);
            RNA4(bg[0][0], bg[0][1], bg[1][0], bg[1][1]);
            ldsm_x4(Us + boff, bu[0][0], bu[0][1], bu[1][0], bu[1][1]);
            RNA4(bu[0][0], bu[0][1], bu[1][0], bu[1][1]);
            #pragma unroll
            for (int mi = 0; mi < 4; mi++) {
                uint32_t a0, a1, a2, a3;
                uint32_t aoff = ((wm * 64 + mi * 16) * STRIDE + k0) * 4 + a_lane;
                ldsm_x4(As + aoff, a0, a1, a2, a3);
                RNA4(a0, a1, a2, a3);
                #pragma unroll
                for (int ni = 0; ni < 2; ni++) {
                    mma_tf32(dg[mi][ni], a0, a1, a2, a3, bg[ni][0], bg[ni][1]);
                    mma_tf32(du[mi][ni], a0, a1, a2, a3, bu[ni][0], bu[ni][1]);
                }
            }
        }
        mbar_arrive(mb_empty + 8 * cs);
        if (++cs == NSTG) { cs = 0; cphase ^= 1; }
    }

    // ---- epilogue: bias + GLU, store rounded h ----
    int g = lane >> 2, tq = lane & 3;
    #pragma unroll
    for (int mi = 0; mi < 4; mi++) {
        #pragma unroll
        for (int half = 0; half < 2; half++) {
            int m = m0 + wm * 64 + mi * 16 + g + half * 8;
            if (m >= cnt) continue;
            size_t rowbase = (size_t)(base + m) * I_DIM;
            #pragma unroll
            for (int ni = 0; ni < 2; ni++) {
                int col = n0 + wn * 16 + ni * 8 + 2 * tq;
                #pragma unroll
                for (int q = 0; q < 2; q++) {
                    float gv = dg[mi][ni][half * 2 + q] + gate_b[(size_t)e * I_DIM + col + q];
                    float uv = du[mi][ni][half * 2 + q] + up_b[(size_t)e * I_DIM + col + q];
                    uv = fminf(fmaxf(uv, -LIMIT), LIMIT);
                    gv = fminf(gv, LIMIT);
                    float glu = gv / (1.0f + __expf(-ALPHA * gv));
                    float h = (uv + 1.0f) * glu;
                    g_hbuf[rowbase + col + q] = __uint_as_float(rnd_tf32(__float_as_uint(h)));
                }
            }
        }
    }
}

// ---------------- K5: down mma.sync tf32 GEMM (128 thr, warp 64x64, 2 CTA/SM) ----------------
__global__ __launch_bounds__(128, 2)
void down_mma(const float* __restrict__ down_w, const float* __restrict__ down_b) {
    int e = blockIdx.z;
    int base = g_offsets[e];
    int cnt  = g_offsets[e + 1] - base;
    int m0 = blockIdx.y * BM;
    if (m0 >= cnt) return;
    int n0 = blockIdx.x * 128;

    extern __shared__ char smem[];
    uint32_t sb0 = smem_u32(smem);
    uint32_t mb_full = sb0;
    uint32_t mb_empty = sb0 + 24;
    float* stages = (float*)(smem + 1024);
    uint32_t sb = sb0 + 1024;

    int tid = threadIdx.x, wid = tid >> 5, lane = tid & 31;
    int wm = wid & 1, wn = wid >> 1;   // 2 x 2 warps, tile 64m x 64n

    if (tid == 0) {
        #pragma unroll
        for (int s = 0; s < NSTG; s++) { mbar_init(mb_full + 8 * s, 128); mbar_init(mb_empty + 8 * s, 128); }
    }
    __syncthreads();

    const float* dwe = down_w + (size_t)e * H_DIM * I_DIM;

    int rr  = tid >> 3;   // 0..15
    int c16 = tid & 7;

    auto load_stage = [&](int s, int k0) {
        float* A = stages + s * DN_STG_F;
        float* B = A + ROW_F;
        uint32_t au = smem_u32(A), bu = smem_u32(B);
        #pragma unroll
        for (int rep = 0; rep < 8; rep++) {
            int row = rr + rep * 16;
            uint32_t d = (row * STRIDE + c16 * 4) * 4;
            int ar = (m0 + row < cnt) ? (base + m0 + row) : base;
            cp16(au + d, g_hbuf + (size_t)ar * I_DIM + k0 + c16 * 4);
            cp16(bu + d, dwe + (size_t)(n0 + row) * I_DIM + k0 + c16 * 4);
        }
    };

    int ps = 0, pp = 1;
    int cs = 0, cphase = 0;

    #pragma unroll
    for (int p = 0; p < 2; p++) {
        mbar_wait(mb_empty + 8 * ps, pp);
        load_stage(ps, p * BK);
        cp_arrive_noinc(mb_full + 8 * ps);
        if (++ps == NSTG) { ps = 0; pp ^= 1; }
    }

    float dd[4][8][4];
    #pragma unroll
    for (int a = 0; a < 4; a++)
        #pragma unroll
        for (int b = 0; b < 8; b++)
            #pragma unroll
            for (int q = 0; q < 4; q++) dd[a][b][q] = 0.f;

    int lr = lane & 7, hi8 = (lane >> 3) & 1, hi16 = (lane >> 4) & 1;
    uint32_t a_lane = ((lr + hi8 * 8) * STRIDE + hi16 * 4) * 4;
    uint32_t b_lane = ((lr + hi16 * 8) * STRIDE + hi8 * 4) * 4;

    for (int c = 0; c < NCHUNK; c++) {
        int nc = c + 2;
        if (nc < NCHUNK) {
            mbar_wait(mb_empty + 8 * ps, pp);
            load_stage(ps, nc * BK);
            cp_arrive_noinc(mb_full + 8 * ps);
            if (++ps == NSTG) { ps = 0; pp ^= 1; }
        }
        mbar_wait(mb_full + 8 * cs, cphase);
        uint32_t As = sb + (uint32_t)(cs * DN_STG_F) * 4;
        uint32_t Bs = As + ROW_F * 4;
        #pragma unroll
        for (int ks = 0; ks < 4; ks++) {
            int k0 = ks * 8;
            uint32_t bb[8][2];
            #pragma unroll
            for (int np = 0; np < 4; np++) {
                uint32_t boff = ((wn * 64 + np * 16) * STRIDE + k0) * 4 + b_lane;
                ldsm_x4(Bs + boff, bb[2*np][0], bb[2*np][1], bb[2*np+1][0], bb[2*np+1][1]);
                RNA4(bb[2*np][0], bb[2*np][1], bb[2*np+1][0], bb[2*np+1][1]);
            }
            #pragma unroll
            for (int mi = 0; mi < 4; mi++) {
                uint32_t a0, a1, a2, a3;
                uint32_t aoff = ((wm * 64 + mi * 16) * STRIDE + k0) * 4 + a_lane;
                ldsm_x4(As + aoff, a0, a1, a2, a3);
                // A (g_hbuf) is already tf32-rounded; no RNA needed
                #pragma unroll
                for (int ni = 0; ni < 8; ni++)
                    mma_tf32(dd[mi][ni], a0, a1, a2, a3, bb[ni][0], bb[ni][1]);
            }
        }
        mbar_arrive(mb_empty + 8 * cs);
        if (++cs == NSTG) { cs = 0; cphase ^= 1; }
    }

    int g = lane >> 2, tq = lane & 3;
    #pragma unroll
    for (int mi = 0; mi < 4; mi++) {
        #pragma unroll
        for (int half = 0; half < 2; half++) {
            int m = m0 + wm * 64 + mi * 16 + g + half * 8;
            if (m >= cnt) continue;
            size_t rowbase = (size_t)(base + m) * H_DIM;
            #pragma unroll
            for (int ni = 0; ni < 8; ni++) {
                int col = n0 + wn * 64 + ni * 8 + 2 * tq;
                float2 v;
                v.x = dd[mi][ni][half * 2 + 0] + down_b[(size_t)e * H_DIM + col];
                v.y = dd[mi][ni][half * 2 + 1] + down_b[(size_t)e * H_DIM + col + 1];
                *(float2*)&g_outp[rowbase + col] = v;
            }
        }
    }
}

// ---------------- K6: combine ----------------
__global__ void combine_kernel(float* __restrict__ out) {
    int t = blockIdx.y;
    int h = blockIdx.x * blockDim.x + threadIdx.x;
    float acc = 0.f;
    #pragma unroll
    for (int s = 0; s < TOPK; s++) {
        float p = g_top_prob[t * TOPK + s];
        int pid = g_pidx[t * TOPK + s];
        acc += p * g_outp[(size_t)pid * H_DIM + h];
    }
    out[(size_t)t * H_DIM + h] = acc;
}

// ---------------- launch ----------------
extern "C" void kernel_launch(void* const* d_in, const int* in_sizes, int n_in,
                              void* d_out, int out_size) {
    const float* hidden   = (const float*)d_in[0];
    const float* router_w = (const float*)d_in[1];
    const float* router_b = (const float*)d_in[2];
    const float* gate_w   = (const float*)d_in[3];
    const float* gate_b   = (const float*)d_in[4];
    const float* up_w     = (const float*)d_in[5];
    const float* up_b     = (const float*)d_in[6];
    const float* down_w   = (const float*)d_in[7];
    const float* down_b   = (const float*)d_in[8];

    float* next_states = (float*)d_out;
    float* score_out   = (float*)d_out + (size_t)T_TOK * H_DIM;

    static bool attr_done = false;
    if (!attr_done) {
        cudaFuncSetAttribute(gateup_mma, cudaFuncAttributeMaxDynamicSharedMemorySize, GU_SMEM);
        cudaFuncSetAttribute(down_mma,   cudaFuncAttributeMaxDynamicSharedMemorySize, DN_SMEM);
        attr_done = true;
    }

    router_kernel<<<T_TOK, 128>>>(hidden, router_w, router_b, score_out);
    route_post<<<1, 1024>>>();

    dim3 gu_grid(I_DIM / 64, NPAIR / BM, N_EXP);
    gateup_mma<<<gu_grid, 256, GU_SMEM>>>(hidden, gate_w, up_w, gate_b, up_b);

    dim3 dn_grid(H_DIM / 128, NPAIR / BM, N_EXP);
    down_mma<<<dn_grid, 128, DN_SMEM>>>(down_w, down_b);

    dim3 cb_grid(H_DIM / 256, T_TOK);
    combine_kernel<<<cb_grid, 256>>>(next_states);
}

// round 14
// speedup vs baseline: 1.0527x; 1.0136x over previous
#include <cuda_runtime.h>
#include <cuda_bf16.h>
#include <cstdint>
#include <math.h>

// ---------------- problem constants ----------------
#define T_TOK 2048
#define H_DIM 2048
#define I_DIM 2048
#define N_EXP 16
#define TOPK  4
#define ALPHA 1.702f
#define LIMIT 7.0f
#define NPAIR (T_TOK * TOPK)   // 8192

#define BM 128
#define BK 32
#define STRIDE 36              // floats per smem row (padded)
#define NCHUNK (H_DIM / BK)    // 64
#define NSTG 3
#define MAX_TILES 80           // ceil-sum of per-expert m-blocks <= 64 + 15

#define ROW_F (128 * STRIDE)            // floats per 128-row tile = 4608
#define HROW_F (64 * STRIDE)            // floats per 64-row tile
#define GU_STG_F (ROW_F + 2 * HROW_F)   // A(128) | Bg(64) | Bu(64) = 9216 floats
#define DN_STG_F (2 * ROW_F)            // A | B = 9216 floats
#define GU_SMEM (1024 + NSTG * GU_STG_F * 4)  // 111,616 B
#define DN_SMEM (1024 + NSTG * DN_STG_F * 4)  // 111,616 B

// ---------------- scratch (device globals) ----------------
__device__ float g_hbuf[(size_t)NPAIR * I_DIM];   // activated hidden per pair (tf32-rounded)
__device__ float g_outp[(size_t)NPAIR * H_DIM];   // per-pair down output
__device__ int   g_pair_token[NPAIR];
__device__ int   g_top_idx[T_TOK * TOPK];
__device__ float g_top_prob[T_TOK * TOPK];
__device__ int   g_pidx[T_TOK * TOPK];
__device__ int   g_offsets[N_EXP + 1];
__device__ int   g_tile_e[MAX_TILES];
__device__ int   g_tile_m0[MAX_TILES];
__device__ int   g_ntiles;

// ---------------- PTX helpers ----------------
__device__ __forceinline__ uint32_t smem_u32(const void* p) {
    uint32_t r;
    asm("{ .reg .u64 t; cvta.to.shared.u64 t, %1; cvt.u32.u64 %0, t; }" : "=r"(r) : "l"(p));
    return r;
}
__device__ __forceinline__ void cp16(uint32_t dst, const void* src) {
    asm volatile("cp.async.cg.shared.global [%0], [%1], 16;" :: "r"(dst), "l"(src) : "memory");
}
// arrive on mbarrier when all of this thread's prior cp.asyncs have completed (no count inc)
__device__ __forceinline__ void cp_arrive_noinc(uint32_t mbar) {
    asm volatile("cp.async.mbarrier.arrive.noinc.shared.b64 [%0];" :: "r"(mbar) : "memory");
}
__device__ __forceinline__ void mbar_init(uint32_t mbar, uint32_t cnt) {
    asm volatile("mbarrier.init.shared.b64 [%0], %1;" :: "r"(mbar), "r"(cnt) : "memory");
}
__device__ __forceinline__ void mbar_arrive(uint32_t mbar) {
    asm volatile("mbarrier.arrive.shared.b64 _, [%0];" :: "r"(mbar) : "memory");
}
__device__ __forceinline__ void mbar_wait(uint32_t mbar, uint32_t phase) {
    asm volatile(
        "{ .reg .pred P;\n"
        "WL_%=: mbarrier.try_wait.parity.acquire.cta.shared::cta.b64 P, [%0], %1, 0x989680;\n"
        "@P bra.uni WD_%=;\n"
        "bra.uni WL_%=;\n"
        "WD_%=: }"
        :: "r"(mbar), "r"(phase) : "memory");
}

__device__ __forceinline__ void ldsm_x4(uint32_t addr, uint32_t& r0, uint32_t& r1, uint32_t& r2, uint32_t& r3) {
    asm volatile("ldmatrix.sync.aligned.m8n8.x4.shared.b16 {%0,%1,%2,%3}, [%4];"
                 : "=r"(r0), "=r"(r1), "=r"(r2), "=r"(r3) : "r"(addr));
}
__device__ __forceinline__ void mma_tf32(float* d, uint32_t a0, uint32_t a1, uint32_t a2, uint32_t a3,
                                         uint32_t b0, uint32_t b1) {
    asm volatile("mma.sync.aligned.m16n8k8.row.col.f32.tf32.tf32.f32 "
                 "{%0,%1,%2,%3}, {%4,%5,%6,%7}, {%8,%9}, {%0,%1,%2,%3};"
                 : "+f"(d[0]), "+f"(d[1]), "+f"(d[2]), "+f"(d[3])
                 : "r"(a0), "r"(a1), "r"(a2), "r"(a3), "r"(b0), "r"(b1));
}
// RNA-to-tf32 in-register: add half-ulp; the MMA HW's RZ truncation completes the round.
#define RNA4(r0, r1, r2, r3) { r0 += 0x1000u; r1 += 0x1000u; r2 += 0x1000u; r3 += 0x1000u; }
// full round (for values stored to memory)
__device__ __forceinline__ uint32_t rnd_tf32(uint32_t u) { return (u + 0x1000u) & 0xFFFFE000u; }

// ---------------- K1: router (no atomics) ----------------
__global__ void router_kernel(const float* __restrict__ x,
                              const float* __restrict__ rw,
                              const float* __restrict__ rb,
                              float* __restrict__ score_out) {
    __shared__ float xs[H_DIM];
    __shared__ float logits[N_EXP];
    int t = blockIdx.x;
    int tid = threadIdx.x;
    const float* xr = x + (size_t)t * H_DIM;
    for (int h = tid; h < H_DIM; h += 128) xs[h] = xr[h];
    __syncthreads();

    int warp = tid >> 5, lane = tid & 31;
    for (int e = warp * 4; e < warp * 4 + 4; e++) {
        const float* w = rw + (size_t)e * H_DIM;
        float acc = 0.f;
        for (int h = lane; h < H_DIM; h += 32) acc += xs[h] * w[h];
        #pragma unroll
        for (int s = 16; s > 0; s >>= 1) acc += __shfl_xor_sync(0xffffffffu, acc, s);
        if (lane == 0) logits[e] = acc + rb[e];
    }
    __syncthreads();

    if (tid == 0) {
        float vals[TOPK]; int idx[TOPK];
        bool used[N_EXP];
        #pragma unroll
        for (int e = 0; e < N_EXP; e++) used[e] = false;
        #pragma unroll
        for (int s = 0; s < TOPK; s++) {
            float best = -INFINITY; int bi = 0;
            for (int e = 0; e < N_EXP; e++)
                if (!used[e] && logits[e] > best) { best = logits[e]; bi = e; }
            used[bi] = true; vals[s] = best; idx[s] = bi;
        }
        float m = vals[0];
        float se = 0.f, pe[TOPK];
        #pragma unroll
        for (int s = 0; s < TOPK; s++) { pe[s] = expf(vals[s] - m); se += pe[s]; }
        float inv = 1.f / se;
        float* row = score_out + (size_t)t * N_EXP;
        #pragma unroll
        for (int e = 0; e < N_EXP; e++) row[e] = 0.f;
        #pragma unroll
        for (int s = 0; s < TOPK; s++) {
            float p = pe[s] * inv;
            row[idx[s]] = p;
            g_top_idx[t * TOPK + s] = idx[s];
            g_top_prob[t * TOPK + s] = p;
        }
    }
}

// ---------------- K2: fused histogram + scan + assign + tile list (single block) ----------------
__global__ __launch_bounds__(1024)
void route_post() {
    __shared__ int cnts[N_EXP];
    __shared__ int offs[N_EXP];
    __shared__ int fill[N_EXP];
    int tid = threadIdx.x;
    if (tid < N_EXP) { cnts[tid] = 0; fill[tid] = 0; }
    __syncthreads();
    for (int i = tid; i < NPAIR; i += 1024)
        atomicAdd(&cnts[g_top_idx[i]], 1);
    __syncthreads();
    if (tid == 0) {
        int off = 0;
        int nt = 0;
        for (int e = 0; e < N_EXP; e++) {
            offs[e] = off; g_offsets[e] = off;
            for (int m0 = 0; m0 < cnts[e]; m0 += BM) {
                g_tile_e[nt] = e; g_tile_m0[nt] = m0; nt++;
            }
            off += cnts[e];
        }
        g_offsets[N_EXP] = off;
        g_ntiles = nt;
    }
    __syncthreads();
    for (int i = tid; i < NPAIR; i += 1024) {
        int e = g_top_idx[i];
        int pos = atomicAdd(&fill[e], 1);
        int pid = offs[e] + pos;
        g_pair_token[pid] = i >> 2;     // token index
        g_pidx[i] = pid;
    }
}

// ---------------- K4: gate+up mma.sync tf32 GEMM + GLU (256 thr, 2x4 warps, BN=64, 2 CTA/SM) ----------------
__global__ __launch_bounds__(256, 2)
void gateup_mma(const float* __restrict__ x,
                const float* __restrict__ gate_w, const float* __restrict__ up_w,
                const float* __restrict__ gate_b, const float* __restrict__ up_b) {
    int ty = blockIdx.y;
    if (ty >= g_ntiles) return;
    int e  = g_tile_e[ty];
    int m0 = g_tile_m0[ty];
    int base = g_offsets[e];
    int cnt  = g_offsets[e + 1] - base;
    int n0 = blockIdx.x * 64;

    extern __shared__ char smem[];
    uint32_t sb0 = smem_u32(smem);
    uint32_t mb_full = sb0;          // 3 x 8B
    uint32_t mb_empty = sb0 + 24;    // 3 x 8B
    int* toks = (int*)(smem + 64);
    float* stages = (float*)(smem + 1024);
    uint32_t sb = sb0 + 1024;

    int tid = threadIdx.x, wid = tid >> 5, lane = tid & 31;
    int wm = wid & 1, wn = wid >> 1;          // 2 m-halves x 4 n-quarters (16 cols each)

    if (tid < 128) {
        int m = m0 + tid;
        toks[tid] = (m < cnt) ? g_pair_token[base + m] : g_pair_token[base];
    }
    if (tid == 0) {
        #pragma unroll
        for (int s = 0; s < NSTG; s++) { mbar_init(mb_full + 8 * s, 256); mbar_init(mb_empty + 8 * s, 256); }
    }
    __syncthreads();

    const float* gwe = gate_w + (size_t)e * I_DIM * H_DIM;
    const float* uwe = up_w   + (size_t)e * I_DIM * H_DIM;

    int rr  = tid >> 3;     // 0..31
    int c16 = tid & 7;      // 16B chunk

    auto load_stage = [&](int s, int k0) {
        float* A = stages + s * GU_STG_F;
        float* Bg = A + ROW_F;
        float* Bu = Bg + HROW_F;
        uint32_t au = smem_u32(A), gu = smem_u32(Bg), uu = smem_u32(Bu);
        #pragma unroll
        for (int rep = 0; rep < 4; rep++) {
            int row = rr + rep * 32;
            uint32_t d = (row * STRIDE + c16 * 4) * 4;
            cp16(au + d, x + (size_t)toks[row] * H_DIM + k0 + c16 * 4);
        }
        #pragma unroll
        for (int rep = 0; rep < 2; rep++) {
            int row = rr + rep * 32;
            uint32_t d = (row * STRIDE + c16 * 4) * 4;
            cp16(gu + d, gwe + (size_t)(n0 + row) * H_DIM + k0 + c16 * 4);
            cp16(uu + d, uwe + (size_t)(n0 + row) * H_DIM + k0 + c16 * 4);
        }
    };

    // pipeline cursors
    int ps = 0, pp = 1;    // producer stage / phase (phase 1: first empty-waits pass)
    int cs = 0, cphase = 0;

    // prime 2 chunks
    #pragma unroll
    for (int p = 0; p < 2; p++) {
        mbar_wait(mb_empty + 8 * ps, pp);
        load_stage(ps, p * BK);
        cp_arrive_noinc(mb_full + 8 * ps);
        if (++ps == NSTG) { ps = 0; pp ^= 1; }
    }

    // accumulators: warp tile 64m x 16n for each of gate/up
    float dg[4][2][4], du[4][2][4];
    #pragma unroll
    for (int a = 0; a < 4; a++)
        #pragma unroll
        for (int b = 0; b < 2; b++)
            #pragma unroll
            for (int q = 0; q < 4; q++) { dg[a][b][q] = 0.f; du[a][b][q] = 0.f; }

    // ldmatrix lane offsets (bytes)
    int lr = lane & 7, hi8 = (lane >> 3) & 1, hi16 = (lane >> 4) & 1;
    uint32_t a_lane = ((lr + hi8 * 8) * STRIDE + hi16 * 4) * 4;   // A x4
    uint32_t b_lane = ((lr + hi16 * 8) * STRIDE + hi8 * 4) * 4;   // B x4 (two n8 tiles)

    for (int c = 0; c < NCHUNK; c++) {
        int nc = c + 2;
        if (nc < NCHUNK) {
            mbar_wait(mb_empty + 8 * ps, pp);
            load_stage(ps, nc * BK);
            cp_arrive_noinc(mb_full + 8 * ps);
            if (++ps == NSTG) { ps = 0; pp ^= 1; }
        }
        mbar_wait(mb_full + 8 * cs, cphase);
        // compute on stage cs
        uint32_t As = sb + (uint32_t)(cs * GU_STG_F) * 4;
        uint32_t Gs = As + ROW_F * 4;
        uint32_t Us = Gs + HROW_F * 4;
        #pragma unroll
        for (int ks = 0; ks < 4; ks++) {
            int k0 = ks * 8;
            uint32_t bg[2][2], bu[2][2];
            uint32_t boff = (wn * 16 * STRIDE + k0) * 4 + b_lane;
            ldsm_x4(Gs + boff, bg[0][0], bg[0][1], bg[1][0], bg[1][1]);
            RNA4(bg[0][0], bg[0][1], bg[1][0], bg[1][1]);
            ldsm_x4(Us + boff, bu[0][0], bu[0][1], bu[1][0], bu[1][1]);
            RNA4(bu[0][0], bu[0][1], bu[1][0], bu[1][1]);
            #pragma unroll
            for (int mi = 0; mi < 4; mi++) {
                uint32_t a0, a1, a2, a3;
                uint32_t aoff = ((wm * 64 + mi * 16) * STRIDE + k0) * 4 + a_lane;
                ldsm_x4(As + aoff, a0, a1, a2, a3);
                RNA4(a0, a1, a2, a3);
                #pragma unroll
                for (int ni = 0; ni < 2; ni++) {
                    mma_tf32(dg[mi][ni], a0, a1, a2, a3, bg[ni][0], bg[ni][1]);
                    mma_tf32(du[mi][ni], a0, a1, a2, a3, bu[ni][0], bu[ni][1]);
                }
            }
        }
        mbar_arrive(mb_empty + 8 * cs);
        if (++cs == NSTG) { cs = 0; cphase ^= 1; }
    }

    // ---- epilogue: bias + GLU, store rounded h ----
    int g = lane >> 2, tq = lane & 3;
    #pragma unroll
    for (int mi = 0; mi < 4; mi++) {
        #pragma unroll
        for (int half = 0; half < 2; half++) {
            int m = m0 + wm * 64 + mi * 16 + g + half * 8;
            if (m >= cnt) continue;
            size_t rowbase = (size_t)(base + m) * I_DIM;
            #pragma unroll
            for (int ni = 0; ni < 2; ni++) {
                int col = n0 + wn * 16 + ni * 8 + 2 * tq;
                #pragma unroll
                for (int q = 0; q < 2; q++) {
                    float gv = dg[mi][ni][half * 2 + q] + gate_b[(size_t)e * I_DIM + col + q];
                    float uv = du[mi][ni][half * 2 + q] + up_b[(size_t)e * I_DIM + col + q];
                    uv = fminf(fmaxf(uv, -LIMIT), LIMIT);
                    gv = fminf(gv, LIMIT);
                    float glu = gv / (1.0f + __expf(-ALPHA * gv));
                    float h = (uv + 1.0f) * glu;
                    g_hbuf[rowbase + col + q] = __uint_as_float(rnd_tf32(__float_as_uint(h)));
                }
            }
        }
    }
}

// ---------------- K5: down mma.sync tf32 GEMM (128 thr, warp 64x64, 2 CTA/SM) ----------------
__global__ __launch_bounds__(128, 2)
void down_mma(const float* __restrict__ down_w, const float* __restrict__ down_b) {
    int ty = blockIdx.y;
    if (ty >= g_ntiles) return;
    int e  = g_tile_e[ty];
    int m0 = g_tile_m0[ty];
    int base = g_offsets[e];
    int cnt  = g_offsets[e + 1] - base;
    int n0 = blockIdx.x * 128;

    extern __shared__ char smem[];
    uint32_t sb0 = smem_u32(smem);
    uint32_t mb_full = sb0;
    uint32_t mb_empty = sb0 + 24;
    float* stages = (float*)(smem + 1024);
    uint32_t sb = sb0 + 1024;

    int tid = threadIdx.x, wid = tid >> 5, lane = tid & 31;
    int wm = wid & 1, wn = wid >> 1;   // 2 x 2 warps, tile 64m x 64n

    if (tid == 0) {
        #pragma unroll
        for (int s = 0; s < NSTG; s++) { mbar_init(mb_full + 8 * s, 128); mbar_init(mb_empty + 8 * s, 128); }
    }
    __syncthreads();

    const float* dwe = down_w + (size_t)e * H_DIM * I_DIM;

    int rr  = tid >> 3;   // 0..15
    int c16 = tid & 7;

    auto load_stage = [&](int s, int k0) {
        float* A = stages + s * DN_STG_F;
        float* B = A + ROW_F;
        uint32_t au = smem_u32(A), bu = smem_u32(B);
        #pragma unroll
        for (int rep = 0; rep < 8; rep++) {
            int row = rr + rep * 16;
            uint32_t d = (row * STRIDE + c16 * 4) * 4;
            int ar = (m0 + row < cnt) ? (base + m0 + row) : base;
            cp16(au + d, g_hbuf + (size_t)ar * I_DIM + k0 + c16 * 4);
            cp16(bu + d, dwe + (size_t)(n0 + row) * I_DIM + k0 + c16 * 4);
        }
    };

    int ps = 0, pp = 1;
    int cs = 0, cphase = 0;

    #pragma unroll
    for (int p = 0; p < 2; p++) {
        mbar_wait(mb_empty + 8 * ps, pp);
        load_stage(ps, p * BK);
        cp_arrive_noinc(mb_full + 8 * ps);
        if (++ps == NSTG) { ps = 0; pp ^= 1; }
    }

    float dd[4][8][4];
    #pragma unroll
    for (int a = 0; a < 4; a++)
        #pragma unroll
        for (int b = 0; b < 8; b++)
            #pragma unroll
            for (int q = 0; q < 4; q++) dd[a][b][q] = 0.f;

    int lr = lane & 7, hi8 = (lane >> 3) & 1, hi16 = (lane >> 4) & 1;
    uint32_t a_lane = ((lr + hi8 * 8) * STRIDE + hi16 * 4) * 4;
    uint32_t b_lane = ((lr + hi16 * 8) * STRIDE + hi8 * 4) * 4;

    for (int c = 0; c < NCHUNK; c++) {
        int nc = c + 2;
        if (nc < NCHUNK) {
            mbar_wait(mb_empty + 8 * ps, pp);
            load_stage(ps, nc * BK);
            cp_arrive_noinc(mb_full + 8 * ps);
            if (++ps == NSTG) { ps = 0; pp ^= 1; }
        }
        mbar_wait(mb_full + 8 * cs, cphase);
        uint32_t As = sb + (uint32_t)(cs * DN_STG_F) * 4;
        uint32_t Bs = As + ROW_F * 4;
        #pragma unroll
        for (int ks = 0; ks < 4; ks++) {
            int k0 = ks * 8;
            uint32_t bb[8][2];
            #pragma unroll
            for (int np = 0; np < 4; np++) {
                uint32_t boff = ((wn * 64 + np * 16) * STRIDE + k0) * 4 + b_lane;
                ldsm_x4(Bs + boff, bb[2*np][0], bb[2*np][1], bb[2*np+1][0], bb[2*np+1][1]);
                RNA4(bb[2*np][0], bb[2*np][1], bb[2*np+1][0], bb[2*np+1][1]);
            }
            #pragma unroll
            for (int mi = 0; mi < 4; mi++) {
                uint32_t a0, a1, a2, a3;
                uint32_t aoff = ((wm * 64 + mi * 16) * STRIDE + k0) * 4 + a_lane;
                ldsm_x4(As + aoff, a0, a1, a2, a3);
                // A (g_hbuf) is already tf32-rounded; no RNA needed
                #pragma unroll
                for (int ni = 0; ni < 8; ni++)
                    mma_tf32(dd[mi][ni], a0, a1, a2, a3, bb[ni][0], bb[ni][1]);
            }
        }
        mbar_arrive(mb_empty + 8 * cs);
        if (++cs == NSTG) { cs = 0; cphase ^= 1; }
    }

    int g = lane >> 2, tq = lane & 3;
    #pragma unroll
    for (int mi = 0; mi < 4; mi++) {
        #pragma unroll
        for (int half = 0; half < 2; half++) {
            int m = m0 + wm * 64 + mi * 16 + g + half * 8;
            if (m >= cnt) continue;
            size_t rowbase = (size_t)(base + m) * H_DIM;
            #pragma unroll
            for (int ni = 0; ni < 8; ni++) {
                int col = n0 + wn * 64 + ni * 8 + 2 * tq;
                float2 v;
                v.x = dd[mi][ni][half * 2 + 0] + down_b[(size_t)e * H_DIM + col];
                v.y = dd[mi][ni][half * 2 + 1] + down_b[(size_t)e * H_DIM + col + 1];
                *(float2*)&g_outp[rowbase + col] = v;
            }
        }
    }
}

// ---------------- K6: combine (float4) ----------------
__global__ void combine_kernel(float* __restrict__ out) {
    int t = blockIdx.y;
    int h4 = blockIdx.x * blockDim.x + threadIdx.x;   // 0..511 (float4 index)
    float4 acc = make_float4(0.f, 0.f, 0.f, 0.f);
    #pragma unroll
    for (int s = 0; s < TOPK; s++) {
        float p = g_top_prob[t * TOPK + s];
        int pid = g_pidx[t * TOPK + s];
        float4 v = ((const float4*)(g_outp + (size_t)pid * H_DIM))[h4];
        acc.x += p * v.x; acc.y += p * v.y; acc.z += p * v.z; acc.w += p * v.w;
    }
    ((float4*)(out + (size_t)t * H_DIM))[h4] = acc;
}

// ---------------- launch ----------------
extern "C" void kernel_launch(void* const* d_in, const int* in_sizes, int n_in,
                              void* d_out, int out_size) {
    const float* hidden   = (const float*)d_in[0];
    const float* router_w = (const float*)d_in[1];
    const float* router_b = (const float*)d_in[2];
    const float* gate_w   = (const float*)d_in[3];
    const float* gate_b   = (const float*)d_in[4];
    const float* up_w     = (const float*)d_in[5];
    const float* up_b     = (const float*)d_in[6];
    const float* down_w   = (const float*)d_in[7];
    const float* down_b   = (const float*)d_in[8];

    float* next_states = (float*)d_out;
    float* score_out   = (float*)d_out + (size_t)T_TOK * H_DIM;

    static bool attr_done = false;
    if (!attr_done) {
        cudaFuncSetAttribute(gateup_mma, cudaFuncAttributeMaxDynamicSharedMemorySize, GU_SMEM);
        cudaFuncSetAttribute(down_mma,   cudaFuncAttributeMaxDynamicSharedMemorySize, DN_SMEM);
        attr_done = true;
    }

    router_kernel<<<T_TOK, 128>>>(hidden, router_w, router_b, score_out);
    route_post<<<1, 1024>>>();

    dim3 gu_grid(I_DIM / 64, MAX_TILES, 1);
    gateup_mma<<<gu_grid, 256, GU_SMEM>>>(hidden, gate_w, up_w, gate_b, up_b);

    dim3 dn_grid(H_DIM / 128, MAX_TILES, 1);
    down_mma<<<dn_grid, 128, DN_SMEM>>>(down_w, down_b);

    dim3 cb_grid(H_DIM / 4 / 256, T_TOK);
    combine_kernel<<<cb_grid, 256>>>(next_states);
}